// round 16
// baseline (speedup 1.0000x reference)
#include <cuda_runtime.h>
#include <cuda_bf16.h>
#include <cstdint>

#define H 128
#define NCOLP 131072
#define NICP  2000
#define NBCP  2000
#define NTOT  (NCOLP + NICP + 2*NBCP)
#define NBLOCKS 148
#define NTHREADS 576
#define NWARPS 18
#define PTS_PER_WARP 4
#define PASS_STRIDE (NBLOCKS * NWARPS * PTS_PER_WARP)   // 10656 points per grid pass

// ---- smem byte offsets ----
// W blocks: for L in 0..2: Wh at L*65536, Wl at L*65536+32768 (each 32KB, [k][n] bf16,
// 256B rows, 16B-chunk XOR swizzle: chunk' = chunk ^ (k&7))
#define SM_W     0
#define SM_CONST 196608
// const floats: [0]=b1,[128]=b2,[256]=b3,[384]=w0x,[512]=w0t,[640]=b0,[768]=W4
#define SMEM_BYTES (SM_CONST + 3584)

__device__ double g_partial[NBLOCKS];
__device__ unsigned g_count = 0;

__device__ __forceinline__ uint32_t smem_to_u32(const void* p) {
    uint32_t a;
    asm("{ .reg .u64 t; cvta.to.shared.u64 t, %1; cvt.u32.u64 %0, t; }"
        : "=r"(a) : "l"(p));
    return a;
}

__device__ __forceinline__ void mma_bf16(float* c, const unsigned* a,
                                         unsigned b0, unsigned b1) {
    asm volatile("mma.sync.aligned.m16n8k16.row.col.f32.bf16.bf16.f32 "
        "{%0,%1,%2,%3}, {%4,%5,%6,%7}, {%8,%9}, {%0,%1,%2,%3};"
        : "+f"(c[0]), "+f"(c[1]), "+f"(c[2]), "+f"(c[3])
        : "r"(a[0]), "r"(a[1]), "r"(a[2]), "r"(a[3]), "r"(b0), "r"(b1));
}
__device__ __forceinline__ void ldsm4t(unsigned* r, uint32_t addr) {
    asm volatile("ldmatrix.sync.aligned.m8n8.x4.trans.shared.b16 {%0,%1,%2,%3}, [%4];"
        : "=r"(r[0]), "=r"(r[1]), "=r"(r[2]), "=r"(r[3]) : "r"(addr));
}

// split val pairs into hi (bf16-rn) + lo (bf16-rn of exact residual)
__device__ __forceinline__ void repack8(const float* val, unsigned* aht, unsigned* alt) {
    #pragma unroll
    for (int q = 0; q < 4; ++q) {
        float v0 = val[2*q], v1 = val[2*q + 1];
        unsigned hp;
        asm("cvt.rn.bf16x2.f32 %0, %1, %2;" : "=r"(hp) : "f"(v1), "f"(v0));
        float h0 = __uint_as_float(hp << 16);           // low half -> f32
        float h1 = __uint_as_float(hp & 0xFFFF0000u);   // high half -> f32
        float l0 = v0 - h0, l1 = v1 - h1;
        unsigned lp;
        asm("cvt.rn.bf16x2.f32 %0, %1, %2;" : "=r"(lp) : "f"(l1), "f"(l0));
        aht[q] = hp; alt[q] = lp;
    }
}

// point fetch + classify (one point)
__device__ __forceinline__ void fetch_pt(int pid,
                                         const float* __restrict__ x_col,
                                         const float* __restrict__ t_col,
                                         const float* __restrict__ x_ic,
                                         const float* __restrict__ t_ic,
                                         const float* __restrict__ x_bcl,
                                         const float* __restrict__ x_bcr,
                                         const float* __restrict__ t_bc,
                                         float& x, float& t, int& ty) {
    x = 0.f; t = 0.f; ty = 3;
    if (pid < NCOLP)                    { x = x_col[pid];               t = t_col[pid];             ty = 0; }
    else if (pid < NCOLP + NICP)        { int q = pid - NCOLP;          x = x_ic[q];  t = t_ic[q];  ty = 1; }
    else if (pid < NCOLP + NICP + NBCP) { int q = pid - NCOLP - NICP;   x = x_bcl[q]; t = t_bc[q];  ty = 2; }
    else if (pid < NTOT)                { int q = pid-NCOLP-NICP-NBCP;  x = x_bcr[q]; t = t_bc[q];  ty = 2; }
}

// one GEMM layer: C[16 tiles][4] = (Ah+Al)*(Wh+Wl), 3 products.
// 2-way np blocking: 4 LDSM then 12 MMAs round-robin over 4 accumulators.
__device__ __forceinline__ void mma_layer(float (&C)[16][4],
                                          const unsigned (&ah)[8][4],
                                          const unsigned (&al)[8][4],
                                          uint32_t whB, uint32_t wlB, int lane) {
    #pragma unroll
    for (int nt = 0; nt < 16; ++nt)
        #pragma unroll
        for (int q = 0; q < 4; ++q) C[nt][q] = 0.f;
    const int g = lane >> 3, lr = lane & 7;
    const int krow = ((g & 1) << 3) + lr;    // row within ktile
    const int ccg  = g >> 1;                 // which n8-chunk of the pair
    #pragma unroll
    for (int kt = 0; kt < 8; ++kt) {
        const int k = 16 * kt + krow;
        const uint32_t rowb = (uint32_t)(k * 256);
        const unsigned kx = (unsigned)(k & 7);
        #pragma unroll
        for (int nb = 0; nb < 4; ++nb) {         // np in blocks of 2
            unsigned bh[2][4], bl[2][4];
            #pragma unroll
            for (int j = 0; j < 2; ++j) {
                int cc = 2 * (nb * 2 + j) + ccg;
                uint32_t off = rowb + (((unsigned)cc ^ kx) << 4);
                ldsm4t(bh[j], whB + off);
                ldsm4t(bl[j], wlB + off);
            }
            #pragma unroll
            for (int j = 0; j < 2; ++j) {        // product Ah*Wh
                int np = nb * 2 + j;
                mma_bf16(C[2*np],   ah[kt], bh[j][0], bh[j][1]);
                mma_bf16(C[2*np+1], ah[kt], bh[j][2], bh[j][3]);
            }
            #pragma unroll
            for (int j = 0; j < 2; ++j) {        // product Al*Wh
                int np = nb * 2 + j;
                mma_bf16(C[2*np],   al[kt], bh[j][0], bh[j][1]);
                mma_bf16(C[2*np+1], al[kt], bh[j][2], bh[j][3]);
            }
            #pragma unroll
            for (int j = 0; j < 2; ++j) {        // product Ah*Wl
                int np = nb * 2 + j;
                mma_bf16(C[2*np],   ah[kt], bl[j][0], bl[j][1]);
                mma_bf16(C[2*np+1], ah[kt], bl[j][2], bl[j][3]);
            }
        }
    }
}

// SiLU-Taylor activation on 8 C-elements of one tile-pair.
__device__ __forceinline__ void act8(float* z, int v, int lane,
                                     const float* sbL, int n0, float* val) {
    if (v == 0) {   // bias only enters the value stream
        float2 ba = *(const float2*)&sbL[n0];
        float2 bb = *(const float2*)&sbL[n0 + 8];
        z[0] += ba.x; z[1] += ba.y; z[2] += ba.x; z[3] += ba.y;
        z[4] += bb.x; z[5] += bb.y; z[6] += bb.x; z[7] += bb.y;
    }
    const int zl = (lane & ~15) | (lane & 3);   // v=0 lane of this (point, col)
    #pragma unroll
    for (int i = 0; i < 8; ++i) {
        float zm = z[i];
        float z0 = __shfl_sync(0xffffffffu, zm, zl);
        float zx = __shfl_sync(0xffffffffu, zm, zl + 4);
        float e   = __expf(-z0);
        float s   = __fdividef(1.f, 1.f + e);
        float s1s = s * (1.f - s);
        float f1  = fmaf(z0, s1s, s);
        float f2  = s1s * fmaf(z0, fmaf(-2.f, s, 1.f), 2.f);
        float av  = z0 * s;                       // value stream
        float dv  = f1 * zm;                      // d/dx, d/dt streams
        float xv  = fmaf(f2 * zx, zx, f1 * zm);   // d2/dx2 stream
        val[i] = (v == 0) ? av : ((v == 3) ? xv : dv);
    }
}

extern "C" __global__ void __launch_bounds__(NTHREADS, 1)
pinn_kernel(const float* __restrict__ x_col, const float* __restrict__ t_col,
            const float* __restrict__ x_ic,  const float* __restrict__ t_ic,
            const float* __restrict__ x_bcl, const float* __restrict__ x_bcr,
            const float* __restrict__ t_bc,
            const float* __restrict__ W0, const float* __restrict__ b0,
            const float* __restrict__ W1, const float* __restrict__ b1,
            const float* __restrict__ W2, const float* __restrict__ b2,
            const float* __restrict__ W3, const float* __restrict__ b3,
            const float* __restrict__ W4, const float* __restrict__ b4,
            const float* __restrict__ pD, const float* __restrict__ pchi,
            float* __restrict__ out)
{
    extern __shared__ char smem[];
    const uint32_t smem_u = smem_to_u32(smem);
    const int tid  = threadIdx.x;
    const int wid  = tid >> 5;
    const int lane = tid & 31;
    const int r0   = lane >> 2;        // 0..7 : lower m-row of this lane
    const int v    = r0 & 3;           // fixed Taylor stream of this lane
    const int cpair = lane & 3;        // col-pair index

    __shared__ double s_red[NWARPS];
    __shared__ int s_last;

    // ---- stage split-bf16 W (k-major, swizzled) + constants ----
    {
        const float* src[3] = {W1, W2, W3};
        for (int L = 0; L < 3; ++L) {
            char* hiB = smem + L * 65536;
            char* loB = hiB + 32768;
            for (int idx = tid; idx < H * H; idx += NTHREADS) {
                int k = idx >> 7, n = idx & 127;
                float f = src[L][idx];
                __nv_bfloat16 bh = __float2bfloat16_rn(f);
                float hiF = __bfloat162float(bh);
                int o = k * 256 + ((((n >> 3) ^ (k & 7)) << 4)) + ((n & 7) << 1);
                *(__nv_bfloat16*)(hiB + o) = bh;
                *(__nv_bfloat16*)(loB + o) = __float2bfloat16_rn(f - hiF);
            }
        }
        float* sc = (float*)(smem + SM_CONST);
        for (int j = tid; j < H; j += NTHREADS) {
            sc[0 * 128 + j] = b1[j];
            sc[1 * 128 + j] = b2[j];
            sc[2 * 128 + j] = b3[j];
            sc[3 * 128 + j] = W0[j];
            sc[4 * 128 + j] = W0[H + j];
            sc[5 * 128 + j] = b0[j];
            sc[6 * 128 + j] = W4[j];
        }
    }
    __syncthreads();

    const float* sc    = (const float*)(smem + SM_CONST);
    const float* s_w0x = sc + 384;
    const float* s_w0t = sc + 512;
    const float* s_b0  = sc + 640;
    const float* s_w4  = sc + 768;
    const float b4v  = __ldg(&b4[0]);
    const float Dv   = __ldg(&pD[0]);
    const float chiv = __ldg(&pchi[0]);

    double local = 0.0;

    const int pa = r0 >> 2, pb = pa + 2;     // this lane's two points (of 4)

    for (int base = (blockIdx.x * NWARPS + wid) * PTS_PER_WARP; base < NTOT;
         base += PASS_STRIDE) {

        // ---- fetch only this lane's two points ----
        float xA, tA, xB, tB; int tyA, tyB;
        fetch_pt(base + pa, x_col, t_col, x_ic, t_ic, x_bcl, x_bcr, t_bc, xA, tA, tyA);
        fetch_pt(base + pb, x_col, t_col, x_ic, t_ic, x_bcl, x_bcr, t_bc, xB, tB, tyB);

        // ---- layer 0: build A-frags directly in registers (identity order) ----
        unsigned ah[8][4], al[8][4];
        #pragma unroll
        for (int kt = 0; kt < 8; ++kt) {
            int k0 = 16 * kt + 2 * cpair;
            float val[8];
            #pragma unroll
            for (int half = 0; half < 2; ++half) {      // k0 / k0+8
                int kk = k0 + 8 * half;
                float2 wx = *(const float2*)&s_w0x[kk];
                float2 wt = *(const float2*)&s_w0t[kk];
                float2 bb = *(const float2*)&s_b0[kk];
                #pragma unroll
                for (int rr = 0; rr < 2; ++rr) {        // rows r0 / r0+8
                    float x = rr ? xB : xA, t = rr ? tB : tA;
                    #pragma unroll
                    for (int e = 0; e < 2; ++e) {       // col kk / kk+1
                        float wxe = e ? wx.y : wx.x;
                        float wte = e ? wt.y : wt.x;
                        float bbe = e ? bb.y : bb.x;
                        float z = fmaf(x, wxe, fmaf(t, wte, bbe));
                        float eb  = __expf(-z);
                        float s   = __fdividef(1.f, 1.f + eb);
                        float s1s = s * (1.f - s);
                        float f1  = fmaf(z, s1s, s);
                        float r;
                        if (v == 0)      r = z * s;
                        else if (v == 1) r = f1 * wxe;
                        else if (v == 2) r = f1 * wte;
                        else {
                            float f2 = s1s * fmaf(z, fmaf(-2.f, s, 1.f), 2.f);
                            r = f2 * wxe * wxe;
                        }
                        val[half * 4 + rr * 2 + e] = r;
                    }
                }
            }
            repack8(val, ah[kt], al[kt]);
        }

        // ---- hidden layers 1,2 with repack; layer 3 with loss epilogue ----
        float C[16][4];
        #pragma unroll 1
        for (int L = 0; L < 2; ++L) {
            mma_layer(C, ah, al, smem_u + L * 65536, smem_u + L * 65536 + 32768, lane);
            const float* sbL = sc + L * 128;
            #pragma unroll
            for (int t = 0; t < 8; ++t) {
                int n0 = 16 * t + 2 * cpair;
                float z[8] = { C[2*t][0], C[2*t][1], C[2*t][2], C[2*t][3],
                               C[2*t+1][0], C[2*t+1][1], C[2*t+1][2], C[2*t+1][3] };
                float val[8];
                act8(z, v, lane, sbL, n0, val);
                repack8(val, ah[t], al[t]);
            }
        }
        mma_layer(C, ah, al, smem_u + 2 * 65536, smem_u + 2 * 65536 + 32768, lane);

        // ---- final activation + W4 dot ----
        float dA = 0.f, dB = 0.f;
        {
            const float* sb3 = sc + 2 * 128;
            #pragma unroll
            for (int t = 0; t < 8; ++t) {
                int n0 = 16 * t + 2 * cpair;
                float z[8] = { C[2*t][0], C[2*t][1], C[2*t][2], C[2*t][3],
                               C[2*t+1][0], C[2*t+1][1], C[2*t+1][2], C[2*t+1][3] };
                float val[8];
                act8(z, v, lane, sb3, n0, val);
                float2 wa = *(const float2*)&s_w4[n0];
                float2 wb = *(const float2*)&s_w4[n0 + 8];
                dA = fmaf(val[0], wa.x, dA); dA = fmaf(val[1], wa.y, dA);
                dA = fmaf(val[4], wb.x, dA); dA = fmaf(val[5], wb.y, dA);
                dB = fmaf(val[2], wa.x, dB); dB = fmaf(val[3], wa.y, dB);
                dB = fmaf(val[6], wb.x, dB); dB = fmaf(val[7], wb.y, dB);
            }
        }
        // reduce over the 4 col-lanes
        dA += __shfl_xor_sync(0xffffffffu, dA, 1);
        dA += __shfl_xor_sync(0xffffffffu, dA, 2);
        dB += __shfl_xor_sync(0xffffffffu, dB, 1);
        dB += __shfl_xor_sync(0xffffffffu, dB, 2);
        // gather the 4 streams of this lane-half's points
        const int gbase = lane & ~15;
        float uA[4], uB[4];
        #pragma unroll
        for (int vv = 0; vv < 4; ++vv) {
            uA[vv] = __shfl_sync(0xffffffffu, dA, gbase | (vv << 2));
            uB[vv] = __shfl_sync(0xffffffffu, dB, gbase | (vv << 2));
        }
        if ((lane & 15) == 0) {
            // this lane's own (xA,tyA) is point pa = lane>>4, (xB,tyB) is pa+2
            float* us[2] = { uA, uB };
            float  xs[2] = { xA, xB };
            int    ts[2] = { tyA, tyB };
            #pragma unroll
            for (int h = 0; h < 2; ++h) {
                float uu  = us[h][0] + b4v;
                float ux  = us[h][1];
                float ut  = us[h][2];
                float uxx = us[h][3];
                float x = xs[h];
                float contrib = 0.f;
                int ty = ts[h];
                if (ty == 0) {
                    float a   = x - 0.7f;
                    float E   = __expf(-50.f * a * a);
                    float dS  = -100.f * a * E;
                    float dS2 = 100.f * E * fmaf(100.f * a, a, -1.f);
                    float res = ut - Dv * uxx + chiv * (ux * dS + uu * dS2);
                    contrib = res * res * (1.f / NCOLP);
                } else if (ty == 1) {
                    float d0  = x - 0.3f;
                    float icv = 0.1f + 0.05f * __expf(-100.f * d0 * d0);
                    float d   = uu - icv;
                    contrib = d * d * (1.f / NICP);
                } else if (ty == 2) {
                    contrib = ux * ux * (1.f / NBCP);
                }
                local += (double)contrib;
            }
        }
    }

    // ---- block sum -> g_partial; last block reduces and writes out ----
    #pragma unroll
    for (int off = 16; off; off >>= 1) {
        long long bits = __shfl_xor_sync(0xffffffffu, __double_as_longlong(local), off);
        local += __longlong_as_double(bits);
    }
    if (lane == 0) s_red[wid] = local;
    __syncthreads();
    if (tid == 0) {
        double s = 0.0;
        #pragma unroll
        for (int w = 0; w < NWARPS; ++w) s += s_red[w];
        g_partial[blockIdx.x] = s;
        __threadfence();
        unsigned old = atomicAdd(&g_count, 1u);
        s_last = (old == NBLOCKS - 1) ? 1 : 0;
        if (s_last) g_count = 0;        // self-reset for next graph replay
    }
    __syncthreads();
    if (s_last) {
        // block-parallel final reduction of 148 partials
        double ps = 0.0;
        for (int b = tid; b < NBLOCKS; b += NTHREADS) ps += g_partial[b];
        #pragma unroll
        for (int off = 16; off; off >>= 1) {
            long long bits = __shfl_xor_sync(0xffffffffu, __double_as_longlong(ps), off);
            ps += __longlong_as_double(bits);
        }
        if (lane == 0) s_red[wid] = ps;
        __syncthreads();
        if (tid == 0) {
            double s = 0.0;
            #pragma unroll
            for (int w = 0; w < NWARPS; ++w) s += s_red[w];
            out[0] = (float)s;
        }
    }
}

extern "C" void kernel_launch(void* const* d_in, const int* in_sizes, int n_in,
                              void* d_out, int out_size) {
    (void)in_sizes; (void)n_in; (void)out_size;
    cudaFuncSetAttribute(pinn_kernel,
                         cudaFuncAttributeMaxDynamicSharedMemorySize, SMEM_BYTES);
    pinn_kernel<<<NBLOCKS, NTHREADS, SMEM_BYTES>>>(
        (const float*)d_in[0],  (const float*)d_in[1],  (const float*)d_in[2],
        (const float*)d_in[3],  (const float*)d_in[4],  (const float*)d_in[5],
        (const float*)d_in[6],  (const float*)d_in[7],  (const float*)d_in[8],
        (const float*)d_in[9],  (const float*)d_in[10], (const float*)d_in[11],
        (const float*)d_in[12], (const float*)d_in[13], (const float*)d_in[14],
        (const float*)d_in[15], (const float*)d_in[16], (const float*)d_in[17],
        (const float*)d_in[18], (float*)d_out);
}

// round 17
// speedup vs baseline: 1.4098x; 1.4098x over previous
#include <cuda_runtime.h>
#include <cuda_bf16.h>
#include <cstdint>

#define H 128
#define NCOLP 131072
#define NICP  2000
#define NBCP  2000
#define NTOT  (NCOLP + NICP + 2*NBCP)
#define NBLOCKS 148
#define NTHREADS 512
#define NWARPS 16
#define PTS_PER_WARP 4
#define NTILES_TOT (NTOT / PTS_PER_WARP)   // 34268 warp-tiles

// ---- smem byte offsets ----
// W blocks: for L in 0..2: Wh at L*65536, Wl at L*65536+32768 (each 32KB, [k][n] bf16,
// 256B rows, 16B-chunk XOR swizzle: chunk' = chunk ^ (k&7))
#define SM_W     0
#define SM_CONST 196608
// const floats: [0]=b1,[128]=b2,[256]=b3,[384]=w0x,[512]=w0t,[640]=b0,[768]=W4
#define SMEM_BYTES (SM_CONST + 3584)

__device__ double g_partial[NBLOCKS];
__device__ unsigned g_count = 0;
__device__ unsigned g_work  = 0;

__device__ __forceinline__ uint32_t smem_to_u32(const void* p) {
    uint32_t a;
    asm("{ .reg .u64 t; cvta.to.shared.u64 t, %1; cvt.u32.u64 %0, t; }"
        : "=r"(a) : "l"(p));
    return a;
}

__device__ __forceinline__ void mma_bf16(float* c, const unsigned* a,
                                         unsigned b0, unsigned b1) {
    asm volatile("mma.sync.aligned.m16n8k16.row.col.f32.bf16.bf16.f32 "
        "{%0,%1,%2,%3}, {%4,%5,%6,%7}, {%8,%9}, {%0,%1,%2,%3};"
        : "+f"(c[0]), "+f"(c[1]), "+f"(c[2]), "+f"(c[3])
        : "r"(a[0]), "r"(a[1]), "r"(a[2]), "r"(a[3]), "r"(b0), "r"(b1));
}
__device__ __forceinline__ void ldsm4t(unsigned* r, uint32_t addr) {
    asm volatile("ldmatrix.sync.aligned.m8n8.x4.trans.shared.b16 {%0,%1,%2,%3}, [%4];"
        : "=r"(r[0]), "=r"(r[1]), "=r"(r[2]), "=r"(r[3]) : "r"(addr));
}

// split val pairs into hi (bf16-rn) + lo (bf16-rn of exact residual)
__device__ __forceinline__ void repack8(const float* val, unsigned* aht, unsigned* alt) {
    #pragma unroll
    for (int q = 0; q < 4; ++q) {
        float v0 = val[2*q], v1 = val[2*q + 1];
        unsigned hp;
        asm("cvt.rn.bf16x2.f32 %0, %1, %2;" : "=r"(hp) : "f"(v1), "f"(v0));
        float h0 = __uint_as_float(hp << 16);           // low half -> f32
        float h1 = __uint_as_float(hp & 0xFFFF0000u);   // high half -> f32
        float l0 = v0 - h0, l1 = v1 - h1;
        unsigned lp;
        asm("cvt.rn.bf16x2.f32 %0, %1, %2;" : "=r"(lp) : "f"(l1), "f"(l0));
        aht[q] = hp; alt[q] = lp;
    }
}

// point fetch + classify (one point)
__device__ __forceinline__ void fetch_pt(int pid,
                                         const float* __restrict__ x_col,
                                         const float* __restrict__ t_col,
                                         const float* __restrict__ x_ic,
                                         const float* __restrict__ t_ic,
                                         const float* __restrict__ x_bcl,
                                         const float* __restrict__ x_bcr,
                                         const float* __restrict__ t_bc,
                                         float& x, float& t, int& ty) {
    x = 0.f; t = 0.f; ty = 3;
    if (pid < NCOLP)                    { x = x_col[pid];               t = t_col[pid];             ty = 0; }
    else if (pid < NCOLP + NICP)        { int q = pid - NCOLP;          x = x_ic[q];  t = t_ic[q];  ty = 1; }
    else if (pid < NCOLP + NICP + NBCP) { int q = pid - NCOLP - NICP;   x = x_bcl[q]; t = t_bc[q];  ty = 2; }
    else if (pid < NTOT)                { int q = pid-NCOLP-NICP-NBCP;  x = x_bcr[q]; t = t_bc[q];  ty = 2; }
}

// one GEMM layer: C[16 tiles][4] = (Ah+Al)*(Wh+Wl), 3 products.
// 2-way np blocking: 4 LDSM then 12 MMAs round-robin over 4 accumulators.
__device__ __forceinline__ void mma_layer(float (&C)[16][4],
                                          const unsigned (&ah)[8][4],
                                          const unsigned (&al)[8][4],
                                          uint32_t whB, uint32_t wlB, int lane) {
    #pragma unroll
    for (int nt = 0; nt < 16; ++nt)
        #pragma unroll
        for (int q = 0; q < 4; ++q) C[nt][q] = 0.f;
    const int g = lane >> 3, lr = lane & 7;
    const int krow = ((g & 1) << 3) + lr;    // row within ktile
    const int ccg  = g >> 1;                 // which n8-chunk of the pair
    #pragma unroll
    for (int kt = 0; kt < 8; ++kt) {
        const int k = 16 * kt + krow;
        const uint32_t rowb = (uint32_t)(k * 256);
        const unsigned kx = (unsigned)(k & 7);
        #pragma unroll
        for (int nb = 0; nb < 4; ++nb) {         // np in blocks of 2
            unsigned bh[2][4], bl[2][4];
            #pragma unroll
            for (int j = 0; j < 2; ++j) {
                int cc = 2 * (nb * 2 + j) + ccg;
                uint32_t off = rowb + (((unsigned)cc ^ kx) << 4);
                ldsm4t(bh[j], whB + off);
                ldsm4t(bl[j], wlB + off);
            }
            #pragma unroll
            for (int j = 0; j < 2; ++j) {        // product Ah*Wh
                int np = nb * 2 + j;
                mma_bf16(C[2*np],   ah[kt], bh[j][0], bh[j][1]);
                mma_bf16(C[2*np+1], ah[kt], bh[j][2], bh[j][3]);
            }
            #pragma unroll
            for (int j = 0; j < 2; ++j) {        // product Al*Wh
                int np = nb * 2 + j;
                mma_bf16(C[2*np],   al[kt], bh[j][0], bh[j][1]);
                mma_bf16(C[2*np+1], al[kt], bh[j][2], bh[j][3]);
            }
            #pragma unroll
            for (int j = 0; j < 2; ++j) {        // product Ah*Wl
                int np = nb * 2 + j;
                mma_bf16(C[2*np],   ah[kt], bl[j][0], bl[j][1]);
                mma_bf16(C[2*np+1], ah[kt], bl[j][2], bl[j][3]);
            }
        }
    }
}

// SiLU-Taylor activation on 8 C-elements of one tile-pair.
__device__ __forceinline__ void act8(float* z, int v, int lane,
                                     const float* sbL, int n0, float* val) {
    if (v == 0) {   // bias only enters the value stream
        float2 ba = *(const float2*)&sbL[n0];
        float2 bb = *(const float2*)&sbL[n0 + 8];
        z[0] += ba.x; z[1] += ba.y; z[2] += ba.x; z[3] += ba.y;
        z[4] += bb.x; z[5] += bb.y; z[6] += bb.x; z[7] += bb.y;
    }
    const int zl = (lane & ~15) | (lane & 3);   // v=0 lane of this (point, col)
    #pragma unroll
    for (int i = 0; i < 8; ++i) {
        float zm = z[i];
        float z0 = __shfl_sync(0xffffffffu, zm, zl);
        float zx = __shfl_sync(0xffffffffu, zm, zl + 4);
        float e   = __expf(-z0);
        float s   = __fdividef(1.f, 1.f + e);
        float s1s = s * (1.f - s);
        float f1  = fmaf(z0, s1s, s);
        float f2  = s1s * fmaf(z0, fmaf(-2.f, s, 1.f), 2.f);
        float av  = z0 * s;                       // value stream
        float dv  = f1 * zm;                      // d/dx, d/dt streams
        float xv  = fmaf(f2 * zx, zx, f1 * zm);   // d2/dx2 stream
        val[i] = (v == 0) ? av : ((v == 3) ? xv : dv);
    }
}

extern "C" __global__ void __launch_bounds__(NTHREADS, 1)
pinn_kernel(const float* __restrict__ x_col, const float* __restrict__ t_col,
            const float* __restrict__ x_ic,  const float* __restrict__ t_ic,
            const float* __restrict__ x_bcl, const float* __restrict__ x_bcr,
            const float* __restrict__ t_bc,
            const float* __restrict__ W0, const float* __restrict__ b0,
            const float* __restrict__ W1, const float* __restrict__ b1,
            const float* __restrict__ W2, const float* __restrict__ b2,
            const float* __restrict__ W3, const float* __restrict__ b3,
            const float* __restrict__ W4, const float* __restrict__ b4,
            const float* __restrict__ pD, const float* __restrict__ pchi,
            float* __restrict__ out)
{
    extern __shared__ char smem[];
    const uint32_t smem_u = smem_to_u32(smem);
    const int tid  = threadIdx.x;
    const int wid  = tid >> 5;
    const int lane = tid & 31;
    const int r0   = lane >> 2;        // 0..7 : lower m-row of this lane
    const int v    = r0 & 3;           // fixed Taylor stream of this lane
    const int cpair = lane & 3;        // col-pair index

    __shared__ double s_red[NWARPS];
    __shared__ int s_last;

    // ---- stage split-bf16 W (k-major, swizzled) + constants ----
    {
        const float* src[3] = {W1, W2, W3};
        for (int L = 0; L < 3; ++L) {
            char* hiB = smem + L * 65536;
            char* loB = hiB + 32768;
            for (int idx = tid; idx < H * H; idx += NTHREADS) {
                int k = idx >> 7, n = idx & 127;
                float f = src[L][idx];
                __nv_bfloat16 bh = __float2bfloat16_rn(f);
                float hiF = __bfloat162float(bh);
                int o = k * 256 + ((((n >> 3) ^ (k & 7)) << 4)) + ((n & 7) << 1);
                *(__nv_bfloat16*)(hiB + o) = bh;
                *(__nv_bfloat16*)(loB + o) = __float2bfloat16_rn(f - hiF);
            }
        }
        float* sc = (float*)(smem + SM_CONST);
        for (int j = tid; j < H; j += NTHREADS) {
            sc[0 * 128 + j] = b1[j];
            sc[1 * 128 + j] = b2[j];
            sc[2 * 128 + j] = b3[j];
            sc[3 * 128 + j] = W0[j];
            sc[4 * 128 + j] = W0[H + j];
            sc[5 * 128 + j] = b0[j];
            sc[6 * 128 + j] = W4[j];
        }
    }
    __syncthreads();

    const float* sc    = (const float*)(smem + SM_CONST);
    const float* s_w0x = sc + 384;
    const float* s_w0t = sc + 512;
    const float* s_b0  = sc + 640;
    const float* s_w4  = sc + 768;
    const float b4v  = __ldg(&b4[0]);
    const float Dv   = __ldg(&pD[0]);
    const float chiv = __ldg(&pchi[0]);

    double local = 0.0;

    const int pa = r0 >> 2, pb = pa + 2;     // this lane's two points (of 4)

    // ---- dynamic warp-level work stealing over 4-point tiles ----
    for (;;) {
        unsigned tile;
        if (lane == 0) tile = atomicAdd(&g_work, 1u);
        tile = __shfl_sync(0xffffffffu, tile, 0);
        if (tile >= (unsigned)NTILES_TOT) break;
        const int base = (int)tile * PTS_PER_WARP;

        // ---- fetch only this lane's two points ----
        float xA, tA, xB, tB; int tyA, tyB;
        fetch_pt(base + pa, x_col, t_col, x_ic, t_ic, x_bcl, x_bcr, t_bc, xA, tA, tyA);
        fetch_pt(base + pb, x_col, t_col, x_ic, t_ic, x_bcl, x_bcr, t_bc, xB, tB, tyB);

        // ---- layer 0: build A-frags directly in registers (identity order) ----
        unsigned ah[8][4], al[8][4];
        #pragma unroll
        for (int kt = 0; kt < 8; ++kt) {
            int k0 = 16 * kt + 2 * cpair;
            float val[8];
            #pragma unroll
            for (int half = 0; half < 2; ++half) {      // k0 / k0+8
                int kk = k0 + 8 * half;
                float2 wx = *(const float2*)&s_w0x[kk];
                float2 wt = *(const float2*)&s_w0t[kk];
                float2 bb = *(const float2*)&s_b0[kk];
                #pragma unroll
                for (int rr = 0; rr < 2; ++rr) {        // rows r0 / r0+8
                    float x = rr ? xB : xA, t = rr ? tB : tA;
                    #pragma unroll
                    for (int e = 0; e < 2; ++e) {       // col kk / kk+1
                        float wxe = e ? wx.y : wx.x;
                        float wte = e ? wt.y : wt.x;
                        float bbe = e ? bb.y : bb.x;
                        float z = fmaf(x, wxe, fmaf(t, wte, bbe));
                        float eb  = __expf(-z);
                        float s   = __fdividef(1.f, 1.f + eb);
                        float s1s = s * (1.f - s);
                        float f1  = fmaf(z, s1s, s);
                        float r;
                        if (v == 0)      r = z * s;
                        else if (v == 1) r = f1 * wxe;
                        else if (v == 2) r = f1 * wte;
                        else {
                            float f2 = s1s * fmaf(z, fmaf(-2.f, s, 1.f), 2.f);
                            r = f2 * wxe * wxe;
                        }
                        val[half * 4 + rr * 2 + e] = r;
                    }
                }
            }
            repack8(val, ah[kt], al[kt]);
        }

        // ---- hidden layers 1,2 with repack; layer 3 with loss epilogue ----
        float C[16][4];
        #pragma unroll 1
        for (int L = 0; L < 2; ++L) {
            mma_layer(C, ah, al, smem_u + L * 65536, smem_u + L * 65536 + 32768, lane);
            const float* sbL = sc + L * 128;
            #pragma unroll
            for (int t = 0; t < 8; ++t) {
                int n0 = 16 * t + 2 * cpair;
                float z[8] = { C[2*t][0], C[2*t][1], C[2*t][2], C[2*t][3],
                               C[2*t+1][0], C[2*t+1][1], C[2*t+1][2], C[2*t+1][3] };
                float val[8];
                act8(z, v, lane, sbL, n0, val);
                repack8(val, ah[t], al[t]);
            }
        }
        mma_layer(C, ah, al, smem_u + 2 * 65536, smem_u + 2 * 65536 + 32768, lane);

        // ---- final activation + W4 dot ----
        float dA = 0.f, dB = 0.f;
        {
            const float* sb3 = sc + 2 * 128;
            #pragma unroll
            for (int t = 0; t < 8; ++t) {
                int n0 = 16 * t + 2 * cpair;
                float z[8] = { C[2*t][0], C[2*t][1], C[2*t][2], C[2*t][3],
                               C[2*t+1][0], C[2*t+1][1], C[2*t+1][2], C[2*t+1][3] };
                float val[8];
                act8(z, v, lane, sb3, n0, val);
                float2 wa = *(const float2*)&s_w4[n0];
                float2 wb = *(const float2*)&s_w4[n0 + 8];
                dA = fmaf(val[0], wa.x, dA); dA = fmaf(val[1], wa.y, dA);
                dA = fmaf(val[4], wb.x, dA); dA = fmaf(val[5], wb.y, dA);
                dB = fmaf(val[2], wa.x, dB); dB = fmaf(val[3], wa.y, dB);
                dB = fmaf(val[6], wb.x, dB); dB = fmaf(val[7], wb.y, dB);
            }
        }
        // reduce over the 4 col-lanes
        dA += __shfl_xor_sync(0xffffffffu, dA, 1);
        dA += __shfl_xor_sync(0xffffffffu, dA, 2);
        dB += __shfl_xor_sync(0xffffffffu, dB, 1);
        dB += __shfl_xor_sync(0xffffffffu, dB, 2);
        // gather the 4 streams of this lane-half's points
        const int gbase = lane & ~15;
        float uA[4], uB[4];
        #pragma unroll
        for (int vv = 0; vv < 4; ++vv) {
            uA[vv] = __shfl_sync(0xffffffffu, dA, gbase | (vv << 2));
            uB[vv] = __shfl_sync(0xffffffffu, dB, gbase | (vv << 2));
        }
        if ((lane & 15) == 0) {
            // this lane's own (xA,tyA) is point pa = lane>>4, (xB,tyB) is pa+2
            float* us[2] = { uA, uB };
            float  xs[2] = { xA, xB };
            int    ts[2] = { tyA, tyB };
            #pragma unroll
            for (int h = 0; h < 2; ++h) {
                float uu  = us[h][0] + b4v;
                float ux  = us[h][1];
                float ut  = us[h][2];
                float uxx = us[h][3];
                float x = xs[h];
                float contrib = 0.f;
                int ty = ts[h];
                if (ty == 0) {
                    float a   = x - 0.7f;
                    float E   = __expf(-50.f * a * a);
                    float dS  = -100.f * a * E;
                    float dS2 = 100.f * E * fmaf(100.f * a, a, -1.f);
                    float res = ut - Dv * uxx + chiv * (ux * dS + uu * dS2);
                    contrib = res * res * (1.f / NCOLP);
                } else if (ty == 1) {
                    float d0  = x - 0.3f;
                    float icv = 0.1f + 0.05f * __expf(-100.f * d0 * d0);
                    float d   = uu - icv;
                    contrib = d * d * (1.f / NICP);
                } else if (ty == 2) {
                    contrib = ux * ux * (1.f / NBCP);
                }
                local += (double)contrib;
            }
        }
    }

    // ---- block sum -> g_partial; last block reduces and writes out ----
    #pragma unroll
    for (int off = 16; off; off >>= 1) {
        long long bits = __shfl_xor_sync(0xffffffffu, __double_as_longlong(local), off);
        local += __longlong_as_double(bits);
    }
    if (lane == 0) s_red[wid] = local;
    __syncthreads();
    if (tid == 0) {
        double s = 0.0;
        #pragma unroll
        for (int w = 0; w < NWARPS; ++w) s += s_red[w];
        g_partial[blockIdx.x] = s;
        __threadfence();
        unsigned old = atomicAdd(&g_count, 1u);
        s_last = (old == NBLOCKS - 1) ? 1 : 0;
        if (s_last) { g_count = 0; g_work = 0; }   // self-reset for next graph replay
    }
    __syncthreads();
    if (s_last) {
        // block-parallel final reduction of 148 partials
        double ps = 0.0;
        for (int b = tid; b < NBLOCKS; b += NTHREADS) ps += g_partial[b];
        #pragma unroll
        for (int off = 16; off; off >>= 1) {
            long long bits = __shfl_xor_sync(0xffffffffu, __double_as_longlong(ps), off);
            ps += __longlong_as_double(bits);
        }
        if (lane == 0) s_red[wid] = ps;
        __syncthreads();
        if (tid == 0) {
            double s = 0.0;
            #pragma unroll
            for (int w = 0; w < NWARPS; ++w) s += s_red[w];
            out[0] = (float)s;
        }
    }
}

extern "C" void kernel_launch(void* const* d_in, const int* in_sizes, int n_in,
                              void* d_out, int out_size) {
    (void)in_sizes; (void)n_in; (void)out_size;
    cudaFuncSetAttribute(pinn_kernel,
                         cudaFuncAttributeMaxDynamicSharedMemorySize, SMEM_BYTES);
    pinn_kernel<<<NBLOCKS, NTHREADS, SMEM_BYTES>>>(
        (const float*)d_in[0],  (const float*)d_in[1],  (const float*)d_in[2],
        (const float*)d_in[3],  (const float*)d_in[4],  (const float*)d_in[5],
        (const float*)d_in[6],  (const float*)d_in[7],  (const float*)d_in[8],
        (const float*)d_in[9],  (const float*)d_in[10], (const float*)d_in[11],
        (const float*)d_in[12], (const float*)d_in[13], (const float*)d_in[14],
        (const float*)d_in[15], (const float*)d_in[16], (const float*)d_in[17],
        (const float*)d_in[18], (float*)d_out);
}